// round 11
// baseline (speedup 1.0000x reference)
#include <cuda_runtime.h>
#include <math.h>

#define SEQ_LEN   65536
#define HIDDEN    1024
#define ROWS_PER_WARP 8
#define K1_WARPS  8                                     // 256 threads
#define K1_BLOCKS (SEQ_LEN / (K1_WARPS * ROWS_PER_WARP)) // 1024
#define EPI_BLOCKS 64                                   // 64 x 256 thr x 4 = 65536

// Scratch (allocation-free requirement -> __device__ globals)
__device__ float    g_bmax[EPI_BLOCKS];
__device__ float    g_psum[EPI_BLOCKS];
__device__ unsigned g_ctr1;
__device__ unsigned g_ctr2;

// ---------------------------------------------------------------------------
// K1: energies[r] = enc[r,:] . hidden
// 256 threads = 8 warps, 8 rows per warp, processed in PAIRS:
// 16 front-batched LDG.128 per lane (MLP=16) spanning two rows, then both
// FMA stages + both reduces. hidden in registers; no smem, no syncthreads.
// Also resets the epilogue's spin counters (stream-ordered before epilogue).
// ---------------------------------------------------------------------------
__global__ __launch_bounds__(256) void matvec_kernel(
    const float* __restrict__ hidden,
    const float* __restrict__ enc,
    float* __restrict__ energies)
{
    if (blockIdx.x == 0 && threadIdx.x == 0) {
        g_ctr1 = 0;
        g_ctr2 = 0;
    }

    const int tid  = threadIdx.x;
    const int warp = tid >> 5;
    const int lane = tid & 31;

    // hidden -> registers: 8 float4 per lane (lane-strided, L1/L2-hot)
    const float4* hp = reinterpret_cast<const float4*>(hidden);
    float4 h[8];
#pragma unroll
    for (int k = 0; k < 8; k++)
        h[k] = hp[lane + k * 32];

    const int row0 = (blockIdx.x * K1_WARPS + warp) * ROWS_PER_WARP;

#pragma unroll 1
    for (int r = 0; r < ROWS_PER_WARP; r += 2) {
        const float4* rpa = reinterpret_cast<const float4*>(
            enc + (size_t)(row0 + r) * HIDDEN);
        const float4* rpb = reinterpret_cast<const float4*>(
            enc + (size_t)(row0 + r + 1) * HIDDEN);

        // Front-batch 16 global loads across two rows (MLP=16)
        float4 va[8], vb[8];
#pragma unroll
        for (int k = 0; k < 8; k++)
            va[k] = rpa[lane + k * 32];
#pragma unroll
        for (int k = 0; k < 8; k++)
            vb[k] = rpb[lane + k * 32];

        // Row A: two accumulators
        float a0 = 0.0f, a1 = 0.0f;
#pragma unroll
        for (int k = 0; k < 8; k += 2) {
            a0 = fmaf(va[k].x,   h[k].x,   a0);
            a0 = fmaf(va[k].y,   h[k].y,   a0);
            a0 = fmaf(va[k].z,   h[k].z,   a0);
            a0 = fmaf(va[k].w,   h[k].w,   a0);
            a1 = fmaf(va[k+1].x, h[k+1].x, a1);
            a1 = fmaf(va[k+1].y, h[k+1].y, a1);
            a1 = fmaf(va[k+1].z, h[k+1].z, a1);
            a1 = fmaf(va[k+1].w, h[k+1].w, a1);
        }
        // Row B: two accumulators
        float b0 = 0.0f, b1 = 0.0f;
#pragma unroll
        for (int k = 0; k < 8; k += 2) {
            b0 = fmaf(vb[k].x,   h[k].x,   b0);
            b0 = fmaf(vb[k].y,   h[k].y,   b0);
            b0 = fmaf(vb[k].z,   h[k].z,   b0);
            b0 = fmaf(vb[k].w,   h[k].w,   b0);
            b1 = fmaf(vb[k+1].x, h[k+1].x, b1);
            b1 = fmaf(vb[k+1].y, h[k+1].y, b1);
            b1 = fmaf(vb[k+1].z, h[k+1].z, b1);
            b1 = fmaf(vb[k+1].w, h[k+1].w, b1);
        }

        float accA = a0 + a1;
        float accB = b0 + b1;
#pragma unroll
        for (int o = 16; o > 0; o >>= 1) {
            accA += __shfl_xor_sync(0xffffffff, accA, o);
            accB += __shfl_xor_sync(0xffffffff, accB, o);
        }

        if (lane == 0) {
            energies[row0 + r]     = accA;
            energies[row0 + r + 1] = accB;
        }
    }
}

// ---------------------------------------------------------------------------
// K2: fused softmax. 64 blocks (all co-resident on 148 SMs -> spin is safe).
// Each block keeps its float4 slice in registers across both barrier phases:
//   phase 1: slice max -> gmem -> spin -> global M (deterministic)
//   phase 2: exp, slice sum -> gmem -> spin -> global Z -> normalized store
// Energies read once, written once.
// ---------------------------------------------------------------------------
__global__ __launch_bounds__(256) void softmax_kernel(float* __restrict__ e)
{
    __shared__ float ws[8];
    const int tid  = threadIdx.x;
    const int lane = tid & 31;
    const int warp = tid >> 5;
    const int i = blockIdx.x * 256 + tid;

    float4 v = reinterpret_cast<const float4*>(e)[i];

    // ---- phase 1: block max ----
    float m = fmaxf(fmaxf(v.x, v.y), fmaxf(v.z, v.w));
#pragma unroll
    for (int o = 16; o > 0; o >>= 1)
        m = fmaxf(m, __shfl_xor_sync(0xffffffff, m, o));
    if (lane == 0) ws[warp] = m;
    __syncthreads();
    float bmax = fmaxf(fmaxf(fmaxf(ws[0], ws[1]), fmaxf(ws[2], ws[3])),
                       fmaxf(fmaxf(ws[4], ws[5]), fmaxf(ws[6], ws[7])));

    if (tid == 0) {
        g_bmax[blockIdx.x] = bmax;
        __threadfence();
        atomicAdd(&g_ctr1, 1u);
        while (*((volatile unsigned*)&g_ctr1) < EPI_BLOCKS)
            __nanosleep(64);
    }
    __syncthreads();
    __threadfence();

    // global max: identical fixed-order reduce in every thread (deterministic)
    float M = -INFINITY;
#pragma unroll
    for (int k = 0; k < EPI_BLOCKS; k++)
        M = fmaxf(M, __ldcg(&g_bmax[k]));

    // ---- phase 2: exp + block sum ----
    v.x = expf(v.x - M);
    v.y = expf(v.y - M);
    v.z = expf(v.z - M);
    v.w = expf(v.w - M);

    float s = (v.x + v.y) + (v.z + v.w);
#pragma unroll
    for (int o = 16; o > 0; o >>= 1)
        s += __shfl_xor_sync(0xffffffff, s, o);
    if (lane == 0) ws[warp] = s;
    __syncthreads();
    float bsum = ((ws[0] + ws[1]) + (ws[2] + ws[3]))
               + ((ws[4] + ws[5]) + (ws[6] + ws[7]));

    if (tid == 0) {
        g_psum[blockIdx.x] = bsum;
        __threadfence();
        atomicAdd(&g_ctr2, 1u);
        while (*((volatile unsigned*)&g_ctr2) < EPI_BLOCKS)
            __nanosleep(64);
    }
    __syncthreads();
    __threadfence();

    // global sum: identical fixed-order reduce (deterministic)
    float Z = 0.0f;
#pragma unroll
    for (int k = 0; k < EPI_BLOCKS; k++)
        Z += __ldcg(&g_psum[k]);
    const float inv = 1.0f / Z;

    v.x *= inv; v.y *= inv; v.z *= inv; v.w *= inv;
    reinterpret_cast<float4*>(e)[i] = v;
}

// ---------------------------------------------------------------------------
extern "C" void kernel_launch(void* const* d_in, const int* in_sizes, int n_in,
                              void* d_out, int out_size)
{
    // Autodetect input order by element count (hidden = 1024, enc = 64M).
    const float* hidden;
    const float* enc;
    if (in_sizes[0] == HIDDEN) {
        hidden = (const float*)d_in[0];
        enc    = (const float*)d_in[1];
    } else {
        enc    = (const float*)d_in[0];
        hidden = (const float*)d_in[1];
    }
    float* out = (float*)d_out;   // [65536] == [1,1,S]

    matvec_kernel<<<K1_BLOCKS, 256>>>(hidden, enc, out);
    softmax_kernel<<<EPI_BLOCKS, 256>>>(out);
}